// round 11
// baseline (speedup 1.0000x reference)
#include <cuda_runtime.h>

#define NN 50000
#define NE 800000

// ---------------- scratch (device globals: no allocations allowed) ----------
__device__ __align__(16) float g_ft[NN * 128];   // per-layer GEMM output
__device__ __align__(16) float g_x[NN * 128];    // layer activations
__device__ float g_p[NN];                        // exp(attention logit) = clamped cos
__device__ int g_rowptr[NN + 1];
__device__ int g_cnt[NN];                        // zero at load; re-zeroed by k_scan
__device__ int g_cursor[NN];
__device__ int g_csrsrc[NE];

// ---------------- CSR build --------------------------------------------------
__global__ void k_count(const int* __restrict__ dst) {
    int e2 = blockIdx.x * blockDim.x + threadIdx.x;
    if (e2 * 2 < NE) {
        int2 d = ((const int2*)dst)[e2];
        atomicAdd(&g_cnt[d.x], 1);
        atomicAdd(&g_cnt[d.y], 1);
    }
}

// single-block scan, shfl-based, 4 elems/thread; re-zeros g_cnt after reading
__global__ void __launch_bounds__(1024) k_scan() {
    __shared__ int wsum[32];
    __shared__ int s_carry, s_tot;
    int tid = threadIdx.x, lane = tid & 31, warp = tid >> 5;
    if (tid == 0) s_carry = 0;
    __syncthreads();
    for (int base = 0; base < NN; base += 4096) {
        int i0 = base + tid * 4;
        int v[4];
#pragma unroll
        for (int j = 0; j < 4; j++) {
            int i = i0 + j;
            v[j] = (i < NN) ? g_cnt[i] : 0;
            if (i < NN) g_cnt[i] = 0;   // restore invariant for next call
        }
        int t = v[0] + v[1] + v[2] + v[3];
        int inc = t;
#pragma unroll
        for (int off = 1; off < 32; off <<= 1) {
            int n = __shfl_up_sync(0xffffffffu, inc, off);
            if (lane >= off) inc += n;
        }
        if (lane == 31) wsum[warp] = inc;
        __syncthreads();
        if (warp == 0) {
            int w = wsum[lane];
            int wi = w;
#pragma unroll
            for (int off = 1; off < 32; off <<= 1) {
                int n = __shfl_up_sync(0xffffffffu, wi, off);
                if (lane >= off) wi += n;
            }
            if (lane == 31) s_tot = wi;
            wsum[lane] = wi - w;  // exclusive
        }
        __syncthreads();
        int run = s_carry + wsum[warp] + (inc - t);
#pragma unroll
        for (int j = 0; j < 4; j++) {
            int i = i0 + j;
            if (i < NN) { g_rowptr[i] = run; g_cursor[i] = run; }
            run += v[j];
        }
        __syncthreads();
        if (tid == 0) s_carry += s_tot;
        __syncthreads();
    }
    if (tid == 0) g_rowptr[NN] = s_carry;
}

__global__ void k_scatter(const int* __restrict__ src, const int* __restrict__ dst) {
    int e2 = blockIdx.x * blockDim.x + threadIdx.x;
    if (e2 * 2 < NE) {
        int2 d = ((const int2*)dst)[e2];
        int2 s = ((const int2*)src)[e2];
        int p0 = atomicAdd(&g_cursor[d.x], 1);
        g_csrsrc[p0] = s.x;
        int p1 = atomicAdd(&g_cursor[d.y], 1);
        g_csrsrc[p1] = s.y;
    }
}

// ---------------- GEMM: ft = X @ W, fused per-row score p_node --------------
// Thread = 2 rows x 32 cols; X tile transposed + pre-duplicated float2 {x,x}.
// Persistent over NTILES row-tiles (uniform single-wave, no tail wave).
//   per k: 2 LDS.64 (x-pairs) + 8 broadcast LDS.128 (W) + 32 FFMA2.
template <int OUTC, bool FROM_X, int NTILES>
__global__ void __launch_bounds__(128, 5) k_gemm(const float* __restrict__ Xin,
                                                 const float* __restrict__ W) {
    constexpr int NCG   = OUTC / 32;      // col groups (4 or 2)
    constexpr int ROWS  = 256 / NCG;      // rows per tile (64 or 128)
    constexpr int XSTR2 = ROWS + 1;       // odd float2 stride -> conflict-free
    __shared__ __align__(16) float sW[32 * OUTC];
    __shared__ __align__(16) float2 sX2[32 * XSTR2];
    __shared__ float ssq[ROWS * NCG];

    const float* X = FROM_X ? (const float*)g_x : Xin;

    int tid  = threadIdx.x;               // 0..127
    int warp = tid >> 5, lane = tid & 31;
    int cg   = warp % NCG;                // which 32-col group
    int half = warp / NCG;                // row half (0 when NCG==4; 0..1 when 2)

#pragma unroll 1
    for (int t = 0; t < NTILES; t++) {
        int rowbase = (blockIdx.x + t * gridDim.x) * ROWS;
        if (rowbase >= NN) break;

        __align__(16) unsigned long long acc[2][16];
#pragma unroll
        for (int r = 0; r < 2; r++)
#pragma unroll
            for (int j = 0; j < 16; j++) acc[r][j] = 0ull;

#pragma unroll 1
        for (int k0 = 0; k0 < 128; k0 += 32) {
            __syncthreads();
            // W tile: 32 x OUTC, vectorized copy
            {
                const float4* Wg = (const float4*)&W[k0 * OUTC];
                float4* sW4 = (float4*)sW;
#pragma unroll
                for (int i = tid; i < 8 * OUTC; i += 128) sW4[i] = Wg[i];
            }
            // X tile transposed + duplicated: sX2[k][row] = {x, x}
            {
                int kk = lane;
#pragma unroll
                for (int r = warp; r < ROWS; r += 4) {
                    int gr = rowbase + r;
                    float xv = (gr < NN) ? X[gr * 128 + k0 + kk] : 0.f;
                    sX2[kk * XSTR2 + r] = make_float2(xv, xv);
                }
            }
            __syncthreads();
#pragma unroll 8
            for (int k = 0; k < 32; k++) {
                unsigned long long xx0 =
                    *(const unsigned long long*)&sX2[k * XSTR2 + half * 64 + lane];
                unsigned long long xx1 =
                    *(const unsigned long long*)&sX2[k * XSTR2 + half * 64 + 32 + lane];
                const ulonglong2* wp = (const ulonglong2*)&sW[k * OUTC + cg * 32];
#pragma unroll
                for (int j = 0; j < 8; j++) {
                    ulonglong2 u = wp[j];   // LDS.128 broadcast
                    asm("fma.rn.f32x2 %0, %1, %2, %0;"
                        : "+l"(acc[0][2 * j]) : "l"(xx0), "l"(u.x));
                    asm("fma.rn.f32x2 %0, %1, %2, %0;"
                        : "+l"(acc[0][2 * j + 1]) : "l"(xx0), "l"(u.y));
                    asm("fma.rn.f32x2 %0, %1, %2, %0;"
                        : "+l"(acc[1][2 * j]) : "l"(xx1), "l"(u.x));
                    asm("fma.rn.f32x2 %0, %1, %2, %0;"
                        : "+l"(acc[1][2 * j + 1]) : "l"(xx1), "l"(u.y));
                }
            }
        }

        // epilogue: store + per-row sum-of-squares
#pragma unroll
        for (int r = 0; r < 2; r++) {
            int lrow = half * 64 + r * 32 + lane;
            int row  = rowbase + lrow;
            float sq = 0.f;
            const float* af = (const float*)acc[r];
#pragma unroll
            for (int j = 0; j < 32; j++) sq += af[j] * af[j];
            if (row < NN) {
                float4* op = (float4*)&g_ft[row * OUTC + cg * 32];
                const float4* ap = (const float4*)acc[r];
#pragma unroll
                for (int j = 0; j < 8; j++) op[j] = ap[j];
            }
            ssq[lrow * NCG + cg] = sq;
        }
        __syncthreads();
        for (int i = tid; i < ROWS; i += 128) {
            if (rowbase + i < NN) {
                float s = 0.f;
#pragma unroll
                for (int c = 0; c < NCG; c++) s += ssq[i * NCG + c];
                float nrm = fmaxf(sqrtf(s), 1e-8f);
                float cs  = s / (nrm * nrm);
                // p = exp(e_node); softmax weights are p[src]/sum(p)
                g_p[rowbase + i] = (cs >= 0.1f) ? cs : 1e-6f;
            }
        }
    }
}

// ---------------- aggregation: warp per dst node, fused softmax+bias(+LN+ReLU)
template <int OUTC, bool LN, bool TO_X>
__global__ void __launch_bounds__(256) k_agg(const float* __restrict__ bias,
                                             const float* __restrict__ lng,
                                             const float* __restrict__ lnb,
                                             float* __restrict__ OUT) {
    constexpr int VEC = OUTC / 32;  // 4 or 2 channels per lane
    int warp = threadIdx.x >> 5, lane = threadIdx.x & 31;
    int node = blockIdx.x * 8 + warp;
    if (node >= NN) return;
    int b = g_rowptr[node], e = g_rowptr[node + 1];

    // phase 1: S = sum over neighbors of p[src]  (lane-strided)
    float S = 0.f;
    for (int j = b + lane; j < e; j += 32) S += g_p[g_csrsrc[j]];
#pragma unroll
    for (int off = 16; off > 0; off >>= 1) S += __shfl_xor_sync(0xffffffffu, S, off);
    float rS = (S > 0.f) ? (1.f / S) : 0.f;

    // phase 2: weighted gather-accumulate
    float acc[VEC];
#pragma unroll
    for (int i = 0; i < VEC; i++) acc[i] = 0.f;

#pragma unroll 8
    for (int j = b; j < e; j++) {
        int s = g_csrsrc[j];                       // uniform across warp
        float w = g_p[s] * rS;
        if constexpr (VEC == 4) {
            float4 f = *(const float4*)&g_ft[s * OUTC + lane * 4];
            acc[0] += w * f.x; acc[1] += w * f.y;
            acc[2] += w * f.z; acc[3] += w * f.w;
        } else {
            float2 f = *(const float2*)&g_ft[s * OUTC + lane * 2];
            acc[0] += w * f.x; acc[1] += w * f.y;
        }
    }

    float v[VEC];
#pragma unroll
    for (int i = 0; i < VEC; i++) v[i] = acc[i] + bias[lane * VEC + i];

    if constexpr (LN) {
        float s = 0.f;
#pragma unroll
        for (int i = 0; i < VEC; i++) s += v[i];
#pragma unroll
        for (int off = 16; off > 0; off >>= 1) s += __shfl_xor_sync(0xffffffffu, s, off);
        float mu = s * (1.0f / OUTC);
        float vs = 0.f;
#pragma unroll
        for (int i = 0; i < VEC; i++) { float d = v[i] - mu; vs += d * d; }
#pragma unroll
        for (int off = 16; off > 0; off >>= 1) vs += __shfl_xor_sync(0xffffffffu, vs, off);
        float inv = rsqrtf(vs * (1.0f / OUTC) + 1e-5f);
        float* dstp = TO_X ? (float*)g_x : OUT;
#pragma unroll
        for (int i = 0; i < VEC; i++) {
            int c = lane * VEC + i;
            float y = (v[i] - mu) * inv * lng[c] + lnb[c];
            dstp[node * OUTC + c] = fmaxf(y, 0.f);
        }
    } else {
        float* dstp = TO_X ? (float*)g_x : OUT;
#pragma unroll
        for (int i = 0; i < VEC; i++) dstp[node * OUTC + lane * VEC + i] = v[i];
    }
}

// ---------------- launch -----------------------------------------------------
extern "C" void kernel_launch(void* const* d_in, const int* in_sizes, int n_in,
                              void* d_out, int out_size) {
    const float* feat = (const float*)d_in[0];
    const int*   src  = (const int*)d_in[1];
    const int*   dst  = (const int*)d_in[2];
    const float* W0   = (const float*)d_in[3];
    const float* b0   = (const float*)d_in[4];
    const float* W1   = (const float*)d_in[5];
    const float* b1   = (const float*)d_in[6];
    const float* W2   = (const float*)d_in[7];
    const float* b2   = (const float*)d_in[8];
    const float* ln1g = (const float*)d_in[9];
    const float* ln1b = (const float*)d_in[10];
    const float* ln2g = (const float*)d_in[11];
    const float* ln2b = (const float*)d_in[12];
    float* out = (float*)d_out;

    const int GE2 = (NE / 2 + 255) / 256;  // 1563
    const int GA  = (NN + 7) / 8;          // 6250

    // 128-col GEMM: 782 row-tiles of 64 -> 391 blocks x 2 tiles (single wave)
    const int G128 = 391;
    // 64-col GEMM: 391 row-tiles of 128 -> already a single wave
    const int G64  = 391;

    // CSR build (rebuilt every call; g_cnt invariant: zero at entry,
    // re-zeroed by k_scan after consumption)
    k_count<<<GE2, 256>>>(dst);
    k_scan<<<1, 1024>>>();
    k_scatter<<<GE2, 256>>>(src, dst);

    // layer 1: feat -> g_x  (conv + LN + ReLU)
    k_gemm<128, false, 2><<<G128, 128>>>(feat, W0);
    k_agg<128, true, true><<<GA, 256>>>(b0, ln1g, ln1b, nullptr);

    // layer 2: g_x -> g_x
    k_gemm<128, true, 2><<<G128, 128>>>(nullptr, W1);
    k_agg<128, true, true><<<GA, 256>>>(b1, ln2g, ln2b, nullptr);

    // layer 3: g_x -> d_out (no LN/ReLU)
    k_gemm<64, true, 1><<<G64, 128>>>(nullptr, W2);
    k_agg<64, false, false><<<GA, 256>>>(b2, nullptr, nullptr, out);
}

// round 12
// speedup vs baseline: 1.0090x; 1.0090x over previous
#include <cuda_runtime.h>

#define NN 50000
#define NE 800000

// ---------------- scratch (device globals: no allocations allowed) ----------
__device__ __align__(16) float g_ft[NN * 128];   // per-layer GEMM output
__device__ __align__(16) float g_x[NN * 128];    // layer activations
__device__ float g_p[NN];                        // exp(attention logit) = clamped cos
__device__ int g_rowptr[NN + 1];
__device__ int g_cnt[NN];                        // zero at load; re-zeroed by k_scan
__device__ int g_cursor[NN];
__device__ int g_csrsrc[NE];
__device__ unsigned int g_tctr[4];               // tile tickets (reset by k_count)

#define CP_A4(dst, src)  asm volatile("cp.async.ca.shared.global [%0], [%1], 4;"  :: "r"(dst), "l"(src))
#define CP_A16(dst, src) asm volatile("cp.async.cg.shared.global [%0], [%1], 16;" :: "r"(dst), "l"(src))
#define CP_COMMIT()      asm volatile("cp.async.commit_group;")
#define CP_WAIT1()       asm volatile("cp.async.wait_group 1;")
#define CP_WAIT0()       asm volatile("cp.async.wait_group 0;")

// ---------------- CSR build --------------------------------------------------
__global__ void k_count(const int* __restrict__ dst) {
    if (blockIdx.x == 0 && threadIdx.x == 0) {
        g_tctr[0] = 0; g_tctr[1] = 0; g_tctr[2] = 0; g_tctr[3] = 0;
    }
    int e2 = blockIdx.x * blockDim.x + threadIdx.x;
    if (e2 * 2 < NE) {
        int2 d = ((const int2*)dst)[e2];
        atomicAdd(&g_cnt[d.x], 1);
        atomicAdd(&g_cnt[d.y], 1);
    }
}

// single-block scan, shfl-based, 4 elems/thread; re-zeros g_cnt after reading
__global__ void __launch_bounds__(1024) k_scan() {
    __shared__ int wsum[32];
    __shared__ int s_carry, s_tot;
    int tid = threadIdx.x, lane = tid & 31, warp = tid >> 5;
    if (tid == 0) s_carry = 0;
    __syncthreads();
    for (int base = 0; base < NN; base += 4096) {
        int i0 = base + tid * 4;
        int v[4];
#pragma unroll
        for (int j = 0; j < 4; j++) {
            int i = i0 + j;
            v[j] = (i < NN) ? g_cnt[i] : 0;
            if (i < NN) g_cnt[i] = 0;   // restore invariant for next call
        }
        int t = v[0] + v[1] + v[2] + v[3];
        int inc = t;
#pragma unroll
        for (int off = 1; off < 32; off <<= 1) {
            int n = __shfl_up_sync(0xffffffffu, inc, off);
            if (lane >= off) inc += n;
        }
        if (lane == 31) wsum[warp] = inc;
        __syncthreads();
        if (warp == 0) {
            int w = wsum[lane];
            int wi = w;
#pragma unroll
            for (int off = 1; off < 32; off <<= 1) {
                int n = __shfl_up_sync(0xffffffffu, wi, off);
                if (lane >= off) wi += n;
            }
            if (lane == 31) s_tot = wi;
            wsum[lane] = wi - w;  // exclusive
        }
        __syncthreads();
        int run = s_carry + wsum[warp] + (inc - t);
#pragma unroll
        for (int j = 0; j < 4; j++) {
            int i = i0 + j;
            if (i < NN) { g_rowptr[i] = run; g_cursor[i] = run; }
            run += v[j];
        }
        __syncthreads();
        if (tid == 0) s_carry += s_tot;
        __syncthreads();
    }
    if (tid == 0) g_rowptr[NN] = s_carry;
}

__global__ void k_scatter(const int* __restrict__ src, const int* __restrict__ dst) {
    int e2 = blockIdx.x * blockDim.x + threadIdx.x;
    if (e2 * 2 < NE) {
        int2 d = ((const int2*)dst)[e2];
        int2 s = ((const int2*)src)[e2];
        int p0 = atomicAdd(&g_cursor[d.x], 1);
        g_csrsrc[p0] = s.x;
        int p1 = atomicAdd(&g_cursor[d.y], 1);
        g_csrsrc[p1] = s.y;
    }
}

// ---------------- GEMM: ft = X @ W, fused per-row score p_node --------------
// Persistent blocks with atomic tile scheduler; cp.async double-buffered
// k-chunk tiles (no load bubbles). Thread = 2 rows x 32 cols.
// X stored [row][33] (conflict-free banks), W read as broadcast LDS.128.
template <int OUTC, bool FROM_X, int CIDX>
__global__ void __launch_bounds__(128, 4) k_gemm(const float* __restrict__ Xin,
                                                 const float* __restrict__ W) {
    constexpr int NCG  = OUTC / 32;       // col groups (4 or 2)
    constexpr int ROWS = 256 / NCG;       // rows per tile (64 or 128)
    constexpr int NT   = (NN + ROWS - 1) / ROWS;
    __shared__ __align__(16) float sW[2][32 * OUTC];
    __shared__ __align__(16) float sX[2][ROWS * 33];
    __shared__ float ssq[ROWS * NCG];
    __shared__ int s_tile;

    const float* X = FROM_X ? (const float*)g_x : Xin;
    int tid = threadIdx.x, warp = tid >> 5, lane = tid & 31;
    int cg = warp % NCG, half = warp / NCG;
    int r0 = half * 64 + lane;

    unsigned int swb[2], sxb[2];
    swb[0] = (unsigned int)__cvta_generic_to_shared(&sW[0][0]);
    swb[1] = (unsigned int)__cvta_generic_to_shared(&sW[1][0]);
    sxb[0] = (unsigned int)__cvta_generic_to_shared(&sX[0][0]);
    sxb[1] = (unsigned int)__cvta_generic_to_shared(&sX[1][0]);

    for (;;) {
        __syncthreads();
        if (tid == 0) s_tile = (int)atomicAdd(&g_tctr[CIDX], 1u);
        __syncthreads();
        int t = s_tile;
        if (t >= NT) break;
        int rowbase = t * ROWS;

        // prefetch chunk 0 -> buffer 0
#pragma unroll
        for (int j = 0; j < OUTC / 16; j++) {
            int c16 = j * 128 + tid;
            CP_A16(swb[0] + c16 * 16, W + c16 * 4);
        }
#pragma unroll
        for (int j = 0; j < ROWS / 4; j++) {
            int i = j * 128 + tid;
            int r = i >> 5, k = i & 31;
            int gr = rowbase + r;
            if (gr < NN) CP_A4(sxb[0] + (r * 33 + k) * 4, X + gr * 128 + k);
        }
        CP_COMMIT();

        __align__(16) unsigned long long acc[2][16];
#pragma unroll
        for (int r = 0; r < 2; r++)
#pragma unroll
            for (int j = 0; j < 16; j++) acc[r][j] = 0ull;

#pragma unroll
        for (int c = 0; c < 4; c++) {
            if (c < 3) {
                int k0 = (c + 1) * 32;
                int nb = (c + 1) & 1;
#pragma unroll
                for (int j = 0; j < OUTC / 16; j++) {
                    int c16 = j * 128 + tid;
                    CP_A16(swb[nb] + c16 * 16, W + k0 * OUTC + c16 * 4);
                }
#pragma unroll
                for (int j = 0; j < ROWS / 4; j++) {
                    int i = j * 128 + tid;
                    int r = i >> 5, k = i & 31;
                    int gr = rowbase + r;
                    if (gr < NN) CP_A4(sxb[nb] + (r * 33 + k) * 4, X + gr * 128 + k0 + k);
                }
                CP_COMMIT();
                CP_WAIT1();
            } else {
                CP_WAIT0();
            }
            __syncthreads();
            const float* xb = sX[c & 1];
            const float* wb = sW[c & 1];
#pragma unroll 8
            for (int k = 0; k < 32; k++) {
                float x0 = xb[r0 * 33 + k];
                float x1 = xb[(r0 + 32) * 33 + k];
                unsigned long long xx0, xx1;
                asm("mov.b64 %0, {%1, %1};" : "=l"(xx0) : "r"(__float_as_uint(x0)));
                asm("mov.b64 %0, {%1, %1};" : "=l"(xx1) : "r"(__float_as_uint(x1)));
                const ulonglong2* wp = (const ulonglong2*)&wb[k * OUTC + cg * 32];
#pragma unroll
                for (int j = 0; j < 8; j++) {
                    ulonglong2 u = wp[j];   // LDS.128 broadcast
                    asm("fma.rn.f32x2 %0, %1, %2, %0;"
                        : "+l"(acc[0][2 * j]) : "l"(xx0), "l"(u.x));
                    asm("fma.rn.f32x2 %0, %1, %2, %0;"
                        : "+l"(acc[0][2 * j + 1]) : "l"(xx0), "l"(u.y));
                    asm("fma.rn.f32x2 %0, %1, %2, %0;"
                        : "+l"(acc[1][2 * j]) : "l"(xx1), "l"(u.x));
                    asm("fma.rn.f32x2 %0, %1, %2, %0;"
                        : "+l"(acc[1][2 * j + 1]) : "l"(xx1), "l"(u.y));
                }
            }
            __syncthreads();
        }

        // epilogue: store + per-row sum-of-squares
#pragma unroll
        for (int r = 0; r < 2; r++) {
            int lrow = r0 + r * 32;
            int row  = rowbase + lrow;
            float sq = 0.f;
            const float* af = (const float*)acc[r];
#pragma unroll
            for (int j = 0; j < 32; j++) sq += af[j] * af[j];
            if (row < NN) {
                float4* op = (float4*)&g_ft[row * OUTC + cg * 32];
                const float4* ap = (const float4*)acc[r];
#pragma unroll
                for (int j = 0; j < 8; j++) op[j] = ap[j];
            }
            ssq[lrow * NCG + cg] = sq;
        }
        __syncthreads();
        for (int i = tid; i < ROWS; i += 128) {
            if (rowbase + i < NN) {
                float s = 0.f;
#pragma unroll
                for (int c = 0; c < NCG; c++) s += ssq[i * NCG + c];
                float nrm = fmaxf(sqrtf(s), 1e-8f);
                float cs  = s / (nrm * nrm);
                // p = exp(e_node); softmax weights are p[src]/sum(p)
                g_p[rowbase + i] = (cs >= 0.1f) ? cs : 1e-6f;
            }
        }
    }
}

// ---------------- aggregation: warp per dst node, fused softmax+bias(+LN+ReLU)
template <int OUTC, bool LN, bool TO_X>
__global__ void __launch_bounds__(256) k_agg(const float* __restrict__ bias,
                                             const float* __restrict__ lng,
                                             const float* __restrict__ lnb,
                                             float* __restrict__ OUT) {
    constexpr int VEC = OUTC / 32;  // 4 or 2 channels per lane
    int warp = threadIdx.x >> 5, lane = threadIdx.x & 31;
    int node = blockIdx.x * 8 + warp;
    if (node >= NN) return;
    int b = g_rowptr[node], e = g_rowptr[node + 1];

    // phase 1: S = sum over neighbors of p[src]  (lane-strided)
    float S = 0.f;
    for (int j = b + lane; j < e; j += 32) S += g_p[g_csrsrc[j]];
#pragma unroll
    for (int off = 16; off > 0; off >>= 1) S += __shfl_xor_sync(0xffffffffu, S, off);
    float rS = (S > 0.f) ? (1.f / S) : 0.f;

    // phase 2: weighted gather-accumulate
    float acc[VEC];
#pragma unroll
    for (int i = 0; i < VEC; i++) acc[i] = 0.f;

#pragma unroll 8
    for (int j = b; j < e; j++) {
        int s = g_csrsrc[j];                       // uniform across warp
        float w = g_p[s] * rS;
        if constexpr (VEC == 4) {
            float4 f = *(const float4*)&g_ft[s * OUTC + lane * 4];
            acc[0] += w * f.x; acc[1] += w * f.y;
            acc[2] += w * f.z; acc[3] += w * f.w;
        } else {
            float2 f = *(const float2*)&g_ft[s * OUTC + lane * 2];
            acc[0] += w * f.x; acc[1] += w * f.y;
        }
    }

    float v[VEC];
#pragma unroll
    for (int i = 0; i < VEC; i++) v[i] = acc[i] + bias[lane * VEC + i];

    if constexpr (LN) {
        float s = 0.f;
#pragma unroll
        for (int i = 0; i < VEC; i++) s += v[i];
#pragma unroll
        for (int off = 16; off > 0; off >>= 1) s += __shfl_xor_sync(0xffffffffu, s, off);
        float mu = s * (1.0f / OUTC);
        float vs = 0.f;
#pragma unroll
        for (int i = 0; i < VEC; i++) { float d = v[i] - mu; vs += d * d; }
#pragma unroll
        for (int off = 16; off > 0; off >>= 1) vs += __shfl_xor_sync(0xffffffffu, vs, off);
        float inv = rsqrtf(vs * (1.0f / OUTC) + 1e-5f);
        float* dstp = TO_X ? (float*)g_x : OUT;
#pragma unroll
        for (int i = 0; i < VEC; i++) {
            int c = lane * VEC + i;
            float y = (v[i] - mu) * inv * lng[c] + lnb[c];
            dstp[node * OUTC + c] = fmaxf(y, 0.f);
        }
    } else {
        float* dstp = TO_X ? (float*)g_x : OUT;
#pragma unroll
        for (int i = 0; i < VEC; i++) dstp[node * OUTC + lane * VEC + i] = v[i];
    }
}

// ---------------- launch -----------------------------------------------------
extern "C" void kernel_launch(void* const* d_in, const int* in_sizes, int n_in,
                              void* d_out, int out_size) {
    const float* feat = (const float*)d_in[0];
    const int*   src  = (const int*)d_in[1];
    const int*   dst  = (const int*)d_in[2];
    const float* W0   = (const float*)d_in[3];
    const float* b0   = (const float*)d_in[4];
    const float* W1   = (const float*)d_in[5];
    const float* b1   = (const float*)d_in[6];
    const float* W2   = (const float*)d_in[7];
    const float* b2   = (const float*)d_in[8];
    const float* ln1g = (const float*)d_in[9];
    const float* ln1b = (const float*)d_in[10];
    const float* ln2g = (const float*)d_in[11];
    const float* ln2b = (const float*)d_in[12];
    float* out = (float*)d_out;

    const int GE2 = (NE / 2 + 255) / 256;  // 1563
    const int GA  = (NN + 7) / 8;          // 6250
    const int GG  = 592;                   // persistent gemm grid (~4 CTAs/SM)

    // CSR build (rebuilt every call; g_cnt invariant: zero at entry,
    // re-zeroed by k_scan after consumption; k_count resets tile tickets)
    k_count<<<GE2, 256>>>(dst);
    k_scan<<<1, 1024>>>();
    k_scatter<<<GE2, 256>>>(src, dst);

    // layer 1: feat -> g_x  (conv + LN + ReLU)
    k_gemm<128, false, 0><<<GG, 128>>>(feat, W0);
    k_agg<128, true, true><<<GA, 256>>>(b0, ln1g, ln1b, nullptr);

    // layer 2: g_x -> g_x
    k_gemm<128, true, 1><<<GG, 128>>>(nullptr, W1);
    k_agg<128, true, true><<<GA, 256>>>(b1, ln2g, ln2b, nullptr);

    // layer 3: g_x -> d_out (no LN/ReLU)
    k_gemm<64, true, 2><<<GG, 128>>>(nullptr, W2);
    k_agg<64, false, false><<<GA, 256>>>(b2, nullptr, nullptr, out);
}

// round 14
// speedup vs baseline: 1.1994x; 1.1887x over previous
#include <cuda_runtime.h>
#include <cuda_bf16.h>
#include <cstdint>

#define NN 50000
#define NE 800000
#define NTILES 391        // tiles of 128 rows

// ---------------- scratch (device globals: no allocations allowed) ----------
__device__ __align__(16) float g_ft[NN * 128];   // per-layer GEMM output
__device__ __align__(16) float g_x[NN * 128];    // layer activations
__device__ float g_p[NN];                        // exp(attention logit) = clamped cos
__device__ int g_rowptr[NN + 1];
__device__ int g_cnt[NN];                        // zero at load; re-zeroed by k_scan
__device__ int g_cursor[NN];
__device__ int g_csrsrc[NE];
// W images: bf16 hi/lo, transposed [n][k], XOR-swizzled word layout
__device__ __align__(16) unsigned short g_whi[3][16384];
__device__ __align__(16) unsigned short g_wlo[3][16384];

#define CVT_BF16X2(res, even, odd) asm("cvt.rn.satfinite.bf16x2.f32 %0, %1, %2;" \
    : "=r"(res) : "f"(odd), "f"(even))
#define CP_A16(dst, src) asm volatile("cp.async.cg.shared.global [%0], [%1], 16;" \
    :: "r"(dst), "l"(src))
#define CP_COMMIT() asm volatile("cp.async.commit_group;")
#define CP_WAIT0()  asm volatile("cp.async.wait_group 0;")

__device__ __forceinline__ uint32_t smem_u32(const void* p) {
    uint32_t a;
    asm("{ .reg .u64 t; cvta.to.shared.u64 t, %1; cvt.u32.u64 %0, t; }" : "=r"(a) : "l"(p));
    return a;
}

// ---------------- CSR build --------------------------------------------------
__global__ void k_count(const int* __restrict__ dst) {
    int e2 = blockIdx.x * blockDim.x + threadIdx.x;
    if (e2 * 2 < NE) {
        int2 d = ((const int2*)dst)[e2];
        atomicAdd(&g_cnt[d.x], 1);
        atomicAdd(&g_cnt[d.y], 1);
    }
}

__global__ void __launch_bounds__(1024) k_scan() {
    __shared__ int wsum[32];
    __shared__ int s_carry, s_tot;
    int tid = threadIdx.x, lane = tid & 31, warp = tid >> 5;
    if (tid == 0) s_carry = 0;
    __syncthreads();
    for (int base = 0; base < NN; base += 4096) {
        int i0 = base + tid * 4;
        int v[4];
#pragma unroll
        for (int j = 0; j < 4; j++) {
            int i = i0 + j;
            v[j] = (i < NN) ? g_cnt[i] : 0;
            if (i < NN) g_cnt[i] = 0;   // restore invariant for next call
        }
        int t = v[0] + v[1] + v[2] + v[3];
        int inc = t;
#pragma unroll
        for (int off = 1; off < 32; off <<= 1) {
            int n = __shfl_up_sync(0xffffffffu, inc, off);
            if (lane >= off) inc += n;
        }
        if (lane == 31) wsum[warp] = inc;
        __syncthreads();
        if (warp == 0) {
            int w = wsum[lane];
            int wi = w;
#pragma unroll
            for (int off = 1; off < 32; off <<= 1) {
                int n = __shfl_up_sync(0xffffffffu, wi, off);
                if (lane >= off) wi += n;
            }
            if (lane == 31) s_tot = wi;
            wsum[lane] = wi - w;
        }
        __syncthreads();
        int run = s_carry + wsum[warp] + (inc - t);
#pragma unroll
        for (int j = 0; j < 4; j++) {
            int i = i0 + j;
            if (i < NN) { g_rowptr[i] = run; g_cursor[i] = run; }
            run += v[j];
        }
        __syncthreads();
        if (tid == 0) s_carry += s_tot;
        __syncthreads();
    }
    if (tid == 0) g_rowptr[NN] = s_carry;
}

__global__ void k_scatter(const int* __restrict__ src, const int* __restrict__ dst) {
    int e2 = blockIdx.x * blockDim.x + threadIdx.x;
    if (e2 * 2 < NE) {
        int2 d = ((const int2*)dst)[e2];
        int2 s = ((const int2*)src)[e2];
        int p0 = atomicAdd(&g_cursor[d.x], 1);
        g_csrsrc[p0] = s.x;
        int p1 = atomicAdd(&g_cursor[d.y], 1);
        g_csrsrc[p1] = s.y;
    }
}

// ---------------- W prep: split fp32 W -> bf16 hi/lo, [n][k] swizzled image -
// word(n, k) = n*64 + ((k>>1) ^ ((n&7)<<2) ^ ((n>>3)&3)), half = k&1
__global__ void k_wprep(const float* __restrict__ W0, const float* __restrict__ W1,
                        const float* __restrict__ W2) {
    int idx = blockIdx.x * blockDim.x + threadIdx.x;
    if (idx >= 16384 * 2 + 8192) return;
    int layer, e, outc;
    const float* W;
    if (idx < 16384)      { layer = 0; e = idx;         outc = 128; W = W0; }
    else if (idx < 32768) { layer = 1; e = idx - 16384; outc = 128; W = W1; }
    else                  { layer = 2; e = idx - 32768; outc = 64;  W = W2; }
    int k = e & 127, n = e >> 7;       // n < outc
    float w = W[k * outc + n];
    __nv_bfloat16 h = __float2bfloat16(w);
    float fh = __bfloat162float(h);
    __nv_bfloat16 l = __float2bfloat16(w - fh);
    int word = n * 64 + (((k >> 1) & 63) ^ ((n & 7) << 2) ^ ((n >> 3) & 3));
    ((unsigned short*)g_whi[layer])[word * 2 + (k & 1)] = __bfloat16_as_ushort(h);
    ((unsigned short*)g_wlo[layer])[word * 2 + (k & 1)] = __bfloat16_as_ushort(l);
}

// ---------------- HMMA GEMM: ft = X @ W (bf16 hi/lo split, 3 passes) --------
// Block = 256 thr / 8 warps, 128-row tile. Warp = 16 rows x OUTC.
// mma.sync.m16n8k16.row.col f32.bf16.bf16 (sm_80 ISA; no 'a' features).
template <int OUTC, bool FROM_X, int LIDX>
__global__ void __launch_bounds__(256) k_hgemm(const float* __restrict__ Xin) {
    constexpr int NTL = OUTC / 8;            // n-tiles per warp (16 or 8)
    constexpr int WWORDS = OUTC * 64;        // u32 words per W image
    extern __shared__ __align__(16) uint32_t sm[];
    uint32_t* sXH = sm;                      // 8192 words (32KB)
    uint32_t* sXL = sm + 8192;               // 8192 words
    uint32_t* sWH = sm + 16384;              // WWORDS
    uint32_t* sWL = sm + 16384 + WWORDS;

    const float* X = FROM_X ? (const float*)g_x : Xin;
    int tid = threadIdx.x, wid = tid >> 5, lane = tid & 31;
    int rowbase = blockIdx.x * 128;

    // W images via cp.async (gmem image already in swizzled layout)
    {
        uint32_t hdst = smem_u32(sWH);
        uint32_t ldst = smem_u32(sWL);
        const char* hsrc = (const char*)g_whi[LIDX];
        const char* lsrc = (const char*)g_wlo[LIDX];
        for (int i = tid; i < WWORDS / 4; i += 256) {
            CP_A16(hdst + i * 16, hsrc + i * 16);
            CP_A16(ldst + i * 16, lsrc + i * 16);
        }
        CP_COMMIT();
    }

    // X tile: fp32 -> bf16 hi/lo, swizzled store (conflict-free, coalesced)
#pragma unroll 4
    for (int it = 0; it < 32; it++) {
        int wl = tid + 256 * it;             // 0..8191 over 128 rows x 64 words
        int r = wl >> 6, w = wl & 63;
        int gr = rowbase + r;
        float2 x = (gr < NN) ? *(const float2*)&X[gr * 128 + 2 * w]
                             : make_float2(0.f, 0.f);
        uint32_t h, l;
        CVT_BF16X2(h, x.x, x.y);             // lo half = col 2w, hi half = 2w+1
        float hx = __uint_as_float(h << 16);
        float hy = __uint_as_float(h & 0xFFFF0000u);
        CVT_BF16X2(l, x.x - hx, x.y - hy);
        int phys = r * 64 + (w ^ ((r & 7) << 2) ^ ((r >> 3) & 3));
        sXH[phys] = h;
        sXL[phys] = l;
    }
    CP_WAIT0();
    __syncthreads();

    // accumulators: warp tile 16 x OUTC
    float d[NTL][4];
#pragma unroll
    for (int nt = 0; nt < NTL; nt++)
#pragma unroll
        for (int j = 0; j < 4; j++) d[nt][j] = 0.f;

    int g = lane >> 2, t = lane & 3;
    int r0 = wid * 16 + g;                   // rows r0 (c0,c1) and r0+8 (c2,c3)
    int r1 = r0 + 8;
    int xm0 = ((r0 & 7) << 2) ^ ((r0 >> 3) & 3);
    int xm1 = ((r1 & 7) << 2) ^ ((r1 >> 3) & 3);
    int base0 = r0 * 64, base1 = r1 * 64;

#pragma unroll 1
    for (int pass = 0; pass < 3; pass++) {   // hi*hi, hi*lo, lo*hi
        const uint32_t* A = (pass == 2) ? sXL : sXH;
        const uint32_t* B = (pass == 1) ? sWL : sWH;
#pragma unroll 1
        for (int ks = 0; ks < 8; ks++) {
            int lw = ks * 8 + t;
            uint32_t a0 = A[base0 + (lw ^ xm0)];
            uint32_t a1 = A[base1 + (lw ^ xm1)];
            uint32_t a2 = A[base0 + ((lw + 4) ^ xm0)];
            uint32_t a3 = A[base1 + ((lw + 4) ^ xm1)];
#pragma unroll
            for (int nt = 0; nt < NTL; nt++) {
                int n = nt * 8 + g;
                int xb = ((n & 7) << 2) ^ (nt & 3);   // (n>>3)&3 == nt&3
                uint32_t b0 = B[n * 64 + (lw ^ xb)];
                uint32_t b1 = B[n * 64 + ((lw + 4) ^ xb)];
                asm volatile(
                    "mma.sync.aligned.m16n8k16.row.col.f32.bf16.bf16.f32 "
                    "{%0,%1,%2,%3}, {%4,%5,%6,%7}, {%8,%9}, {%0,%1,%2,%3};"
                    : "+f"(d[nt][0]), "+f"(d[nt][1]), "+f"(d[nt][2]), "+f"(d[nt][3])
                    : "r"(a0), "r"(a1), "r"(a2), "r"(a3), "r"(b0), "r"(b1));
            }
        }
    }

    // epilogue: store rows + per-row sum-of-squares -> p score
    float sq0 = 0.f, sq1 = 0.f;
    int row0 = rowbase + r0, row1 = rowbase + r1;
#pragma unroll
    for (int nt = 0; nt < NTL; nt++) {
        sq0 += d[nt][0] * d[nt][0] + d[nt][1] * d[nt][1];
        sq1 += d[nt][2] * d[nt][2] + d[nt][3] * d[nt][3];
        if (row0 < NN)
            *(float2*)&g_ft[row0 * OUTC + nt * 8 + 2 * t] = make_float2(d[nt][0], d[nt][1]);
        if (row1 < NN)
            *(float2*)&g_ft[row1 * OUTC + nt * 8 + 2 * t] = make_float2(d[nt][2], d[nt][3]);
    }
    sq0 += __shfl_xor_sync(0xffffffffu, sq0, 1);
    sq0 += __shfl_xor_sync(0xffffffffu, sq0, 2);
    sq1 += __shfl_xor_sync(0xffffffffu, sq1, 1);
    sq1 += __shfl_xor_sync(0xffffffffu, sq1, 2);
    if (t == 0) {
        if (row0 < NN) {
            float nrm = fmaxf(sqrtf(sq0), 1e-8f);
            float cs  = sq0 / (nrm * nrm);
            g_p[row0] = (cs >= 0.1f) ? cs : 1e-6f;
        }
        if (row1 < NN) {
            float nrm = fmaxf(sqrtf(sq1), 1e-8f);
            float cs  = sq1 / (nrm * nrm);
            g_p[row1] = (cs >= 0.1f) ? cs : 1e-6f;
        }
    }
}

// ---------------- aggregation: warp per dst node, fused softmax+bias(+LN+ReLU)
template <int OUTC, bool LN, bool TO_X>
__global__ void __launch_bounds__(256) k_agg(const float* __restrict__ bias,
                                             const float* __restrict__ lng,
                                             const float* __restrict__ lnb,
                                             float* __restrict__ OUT) {
    constexpr int VEC = OUTC / 32;
    int warp = threadIdx.x >> 5, lane = threadIdx.x & 31;
    int node = blockIdx.x * 8 + warp;
    if (node >= NN) return;
    int b = g_rowptr[node], e = g_rowptr[node + 1];

    float S = 0.f;
    for (int j = b + lane; j < e; j += 32) S += g_p[g_csrsrc[j]];
#pragma unroll
    for (int off = 16; off > 0; off >>= 1) S += __shfl_xor_sync(0xffffffffu, S, off);
    float rS = (S > 0.f) ? (1.f / S) : 0.f;

    float acc[VEC];
#pragma unroll
    for (int i = 0; i < VEC; i++) acc[i] = 0.f;

#pragma unroll 8
    for (int j = b; j < e; j++) {
        int s = g_csrsrc[j];
        float w = g_p[s] * rS;
        if constexpr (VEC == 4) {
            float4 f = *(const float4*)&g_ft[s * OUTC + lane * 4];
            acc[0] += w * f.x; acc[1] += w * f.y;
            acc[2] += w * f.z; acc[3] += w * f.w;
        } else {
            float2 f = *(const float2*)&g_ft[s * OUTC + lane * 2];
            acc[0] += w * f.x; acc[1] += w * f.y;
        }
    }

    float v[VEC];
#pragma unroll
    for (int i = 0; i < VEC; i++) v[i] = acc[i] + bias[lane * VEC + i];

    if constexpr (LN) {
        float s = 0.f;
#pragma unroll
        for (int i = 0; i < VEC; i++) s += v[i];
#pragma unroll
        for (int off = 16; off > 0; off >>= 1) s += __shfl_xor_sync(0xffffffffu, s, off);
        float mu = s * (1.0f / OUTC);
        float vs = 0.f;
#pragma unroll
        for (int i = 0; i < VEC; i++) { float dd = v[i] - mu; vs += dd * dd; }
#pragma unroll
        for (int off = 16; off > 0; off >>= 1) vs += __shfl_xor_sync(0xffffffffu, vs, off);
        float inv = rsqrtf(vs * (1.0f / OUTC) + 1e-5f);
        float* dstp = TO_X ? (float*)g_x : OUT;
#pragma unroll
        for (int i = 0; i < VEC; i++) {
            int c = lane * VEC + i;
            float y = (v[i] - mu) * inv * lng[c] + lnb[c];
            dstp[node * OUTC + c] = fmaxf(y, 0.f);
        }
    } else {
        float* dstp = TO_X ? (float*)g_x : OUT;
#pragma unroll
        for (int i = 0; i < VEC; i++) dstp[node * OUTC + lane * VEC + i] = v[i];
    }
}

// ---------------- launch -----------------------------------------------------
extern "C" void kernel_launch(void* const* d_in, const int* in_sizes, int n_in,
                              void* d_out, int out_size) {
    const float* feat = (const float*)d_in[0];
    const int*   src  = (const int*)d_in[1];
    const int*   dst  = (const int*)d_in[2];
    const float* W0   = (const float*)d_in[3];
    const float* b0   = (const float*)d_in[4];
    const float* W1   = (const float*)d_in[5];
    const float* b1   = (const float*)d_in[6];
    const float* W2   = (const float*)d_in[7];
    const float* b2   = (const float*)d_in[8];
    const float* ln1g = (const float*)d_in[9];
    const float* ln1b = (const float*)d_in[10];
    const float* ln2g = (const float*)d_in[11];
    const float* ln2b = (const float*)d_in[12];
    float* out = (float*)d_out;

    const int GE2 = (NE / 2 + 255) / 256;
    const int GA  = (NN + 7) / 8;
    const int S128 = (16384 + 2 * 128 * 64) * 4;   // 128KB
    const int S64  = (16384 + 2 * 64 * 64) * 4;    // 96KB

    cudaFuncSetAttribute(k_hgemm<128, false, 0>,
                         cudaFuncAttributeMaxDynamicSharedMemorySize, S128);
    cudaFuncSetAttribute(k_hgemm<128, true, 1>,
                         cudaFuncAttributeMaxDynamicSharedMemorySize, S128);
    cudaFuncSetAttribute(k_hgemm<64, true, 2>,
                         cudaFuncAttributeMaxDynamicSharedMemorySize, S64);

    // W split-prep + CSR build (deterministic, rebuilt every call)
    k_wprep<<<(40960 + 255) / 256, 256>>>(W0, W1, W2);
    k_count<<<GE2, 256>>>(dst);
    k_scan<<<1, 1024>>>();
    k_scatter<<<GE2, 256>>>(src, dst);

    // layer 1: feat -> g_x  (conv + LN + ReLU)
    k_hgemm<128, false, 0><<<NTILES, 256, S128>>>(feat);
    k_agg<128, true, true><<<GA, 256>>>(b0, ln1g, ln1b, nullptr);

    // layer 2: g_x -> g_x
    k_hgemm<128, true, 1><<<NTILES, 256, S128>>>(nullptr);
    k_agg<128, true, true><<<GA, 256>>>(b1, ln2g, ln2b, nullptr);

    // layer 3: g_x -> d_out (no LN/ReLU)
    k_hgemm<64, true, 2><<<NTILES, 256, S64>>>(nullptr);
    k_agg<64, false, false><<<GA, 256>>>(b2, nullptr, nullptr, out);
}

// round 15
// speedup vs baseline: 1.2111x; 1.0098x over previous
#include <cuda_runtime.h>
#include <cuda_bf16.h>
#include <cstdint>

#define NN 50000
#define NE 800000
#define NTILES 391        // tiles of 128 rows

// ---------------- scratch (device globals: no allocations allowed) ----------
__device__ __align__(16) float g_ft[NN * 128];   // per-layer GEMM output
__device__ __align__(16) float g_x[NN * 128];    // layer activations
__device__ float g_p[NN];                        // exp(attention logit) = clamped cos
__device__ int g_rowptr[NN + 1];
__device__ int g_cnt[NN];                        // zero at load; re-zeroed by k_scan
__device__ int g_cursor[NN];
__device__ int g_csrsrc[NE];
// W images: bf16 hi/lo, transposed [n][k], XOR-swizzled word layout
__device__ __align__(16) unsigned short g_whi[3][16384];
__device__ __align__(16) unsigned short g_wlo[3][16384];

#define CVT_BF16X2(res, even, odd) asm("cvt.rn.satfinite.bf16x2.f32 %0, %1, %2;" \
    : "=r"(res) : "f"(odd), "f"(even))
#define CP_A16(dst, src) asm volatile("cp.async.cg.shared.global [%0], [%1], 16;" \
    :: "r"(dst), "l"(src))
#define CP_COMMIT() asm volatile("cp.async.commit_group;")
#define CP_WAIT0()  asm volatile("cp.async.wait_group 0;")

__device__ __forceinline__ uint32_t smem_u32(const void* p) {
    uint32_t a;
    asm("{ .reg .u64 t; cvta.to.shared.u64 t, %1; cvt.u32.u64 %0, t; }" : "=r"(a) : "l"(p));
    return a;
}

// ---------------- fused W prep + degree count --------------------------------
// blocks [0,160): split fp32 W -> bf16 hi/lo swizzled images
// blocks [160,160+782): count edge degrees, 4 edges/thread (ILP)
__global__ void k_wprep_count(const float* __restrict__ W0,
                              const float* __restrict__ W1,
                              const float* __restrict__ W2,
                              const int* __restrict__ dst) {
    if (blockIdx.x < 160) {
        int idx = blockIdx.x * 256 + threadIdx.x;
        if (idx >= 16384 * 2 + 8192) return;
        int layer, e, outc;
        const float* W;
        if (idx < 16384)      { layer = 0; e = idx;         outc = 128; W = W0; }
        else if (idx < 32768) { layer = 1; e = idx - 16384; outc = 128; W = W1; }
        else                  { layer = 2; e = idx - 32768; outc = 64;  W = W2; }
        int k = e & 127, n = e >> 7;
        float w = W[k * outc + n];
        __nv_bfloat16 h = __float2bfloat16(w);
        float fh = __bfloat162float(h);
        __nv_bfloat16 l = __float2bfloat16(w - fh);
        int word = n * 64 + (((k >> 1) & 63) ^ ((n & 7) << 2) ^ ((n >> 3) & 3));
        ((unsigned short*)g_whi[layer])[word * 2 + (k & 1)] = __bfloat16_as_ushort(h);
        ((unsigned short*)g_wlo[layer])[word * 2 + (k & 1)] = __bfloat16_as_ushort(l);
    } else {
        int e4 = (blockIdx.x - 160) * 256 + threadIdx.x;
        if (e4 < NE / 4) {
            int4 d = ((const int4*)dst)[e4];
            atomicAdd(&g_cnt[d.x], 1);
            atomicAdd(&g_cnt[d.y], 1);
            atomicAdd(&g_cnt[d.z], 1);
            atomicAdd(&g_cnt[d.w], 1);
        }
    }
}

// single-block scan, shfl-based, 4 elems/thread; re-zeros g_cnt after reading
__global__ void __launch_bounds__(1024) k_scan() {
    __shared__ int wsum[32];
    __shared__ int s_carry, s_tot;
    int tid = threadIdx.x, lane = tid & 31, warp = tid >> 5;
    if (tid == 0) s_carry = 0;
    __syncthreads();
    for (int base = 0; base < NN; base += 4096) {
        int i0 = base + tid * 4;
        int v[4];
#pragma unroll
        for (int j = 0; j < 4; j++) {
            int i = i0 + j;
            v[j] = (i < NN) ? g_cnt[i] : 0;
            if (i < NN) g_cnt[i] = 0;   // restore invariant for next call
        }
        int t = v[0] + v[1] + v[2] + v[3];
        int inc = t;
#pragma unroll
        for (int off = 1; off < 32; off <<= 1) {
            int n = __shfl_up_sync(0xffffffffu, inc, off);
            if (lane >= off) inc += n;
        }
        if (lane == 31) wsum[warp] = inc;
        __syncthreads();
        if (warp == 0) {
            int w = wsum[lane];
            int wi = w;
#pragma unroll
            for (int off = 1; off < 32; off <<= 1) {
                int n = __shfl_up_sync(0xffffffffu, wi, off);
                if (lane >= off) wi += n;
            }
            if (lane == 31) s_tot = wi;
            wsum[lane] = wi - w;
        }
        __syncthreads();
        int run = s_carry + wsum[warp] + (inc - t);
#pragma unroll
        for (int j = 0; j < 4; j++) {
            int i = i0 + j;
            if (i < NN) { g_rowptr[i] = run; g_cursor[i] = run; }
            run += v[j];
        }
        __syncthreads();
        if (tid == 0) s_carry += s_tot;
        __syncthreads();
    }
    if (tid == 0) g_rowptr[NN] = s_carry;
}

__global__ void k_scatter(const int* __restrict__ src, const int* __restrict__ dst) {
    int e4 = blockIdx.x * blockDim.x + threadIdx.x;
    if (e4 < NE / 4) {
        int4 d = ((const int4*)dst)[e4];
        int4 s = ((const int4*)src)[e4];
        int p0 = atomicAdd(&g_cursor[d.x], 1);
        int p1 = atomicAdd(&g_cursor[d.y], 1);
        int p2 = atomicAdd(&g_cursor[d.z], 1);
        int p3 = atomicAdd(&g_cursor[d.w], 1);
        g_csrsrc[p0] = s.x;
        g_csrsrc[p1] = s.y;
        g_csrsrc[p2] = s.z;
        g_csrsrc[p3] = s.w;
    }
}

// ---------------- HMMA GEMM: ft = X @ W (bf16 hi/lo split, 3 passes) --------
// Block = 256 thr / 8 warps, 128-row tile. Warp = 16 rows x OUTC.
// mma.sync.m16n8k16.row.col f32.bf16.bf16 (sm_80 ISA; no 'a' features).
template <int OUTC, bool FROM_X, int LIDX>
__global__ void __launch_bounds__(256) k_hgemm(const float* __restrict__ Xin) {
    constexpr int NTL = OUTC / 8;            // n-tiles per warp (16 or 8)
    constexpr int WWORDS = OUTC * 64;        // u32 words per W image
    extern __shared__ __align__(16) uint32_t sm[];
    uint32_t* sXH = sm;                      // 8192 words (32KB)
    uint32_t* sXL = sm + 8192;               // 8192 words
    uint32_t* sWH = sm + 16384;              // WWORDS
    uint32_t* sWL = sm + 16384 + WWORDS;

    const float* X = FROM_X ? (const float*)g_x : Xin;
    int tid = threadIdx.x, wid = tid >> 5, lane = tid & 31;
    int rowbase = blockIdx.x * 128;

    // W images via cp.async (gmem image already in swizzled layout)
    {
        uint32_t hdst = smem_u32(sWH);
        uint32_t ldst = smem_u32(sWL);
        const char* hsrc = (const char*)g_whi[LIDX];
        const char* lsrc = (const char*)g_wlo[LIDX];
        for (int i = tid; i < WWORDS / 4; i += 256) {
            CP_A16(hdst + i * 16, hsrc + i * 16);
            CP_A16(ldst + i * 16, lsrc + i * 16);
        }
        CP_COMMIT();
    }

    // X tile: fp32 -> bf16 hi/lo, swizzled store (conflict-free, coalesced)
#pragma unroll 4
    for (int it = 0; it < 32; it++) {
        int wl = tid + 256 * it;             // 0..8191 over 128 rows x 64 words
        int r = wl >> 6, w = wl & 63;
        int gr = rowbase + r;
        float2 x = (gr < NN) ? *(const float2*)&X[gr * 128 + 2 * w]
                             : make_float2(0.f, 0.f);
        uint32_t h, l;
        CVT_BF16X2(h, x.x, x.y);             // lo half = col 2w, hi half = 2w+1
        float hx = __uint_as_float(h << 16);
        float hy = __uint_as_float(h & 0xFFFF0000u);
        CVT_BF16X2(l, x.x - hx, x.y - hy);
        int phys = r * 64 + (w ^ ((r & 7) << 2) ^ ((r >> 3) & 3));
        sXH[phys] = h;
        sXL[phys] = l;
    }
    CP_WAIT0();
    __syncthreads();

    // accumulators: warp tile 16 x OUTC
    float d[NTL][4];
#pragma unroll
    for (int nt = 0; nt < NTL; nt++)
#pragma unroll
        for (int j = 0; j < 4; j++) d[nt][j] = 0.f;

    int g = lane >> 2, t = lane & 3;
    int r0 = wid * 16 + g;                   // rows r0 (c0,c1) and r0+8 (c2,c3)
    int r1 = r0 + 8;
    int xm0 = ((r0 & 7) << 2) ^ ((r0 >> 3) & 3);
    int xm1 = ((r1 & 7) << 2) ^ ((r1 >> 3) & 3);
    int base0 = r0 * 64, base1 = r1 * 64;

#pragma unroll 1
    for (int pass = 0; pass < 3; pass++) {   // hi*hi, hi*lo, lo*hi
        const uint32_t* A = (pass == 2) ? sXL : sXH;
        const uint32_t* B = (pass == 1) ? sWL : sWH;
#pragma unroll 1
        for (int ks = 0; ks < 8; ks++) {
            int lw = ks * 8 + t;
            uint32_t a0 = A[base0 + (lw ^ xm0)];
            uint32_t a1 = A[base1 + (lw ^ xm1)];
            uint32_t a2 = A[base0 + ((lw + 4) ^ xm0)];
            uint32_t a3 = A[base1 + ((lw + 4) ^ xm1)];
#pragma unroll
            for (int nt = 0; nt < NTL; nt++) {
                int n = nt * 8 + g;
                int xb = ((n & 7) << 2) ^ (nt & 3);   // (n>>3)&3 == nt&3
                uint32_t b0 = B[n * 64 + (lw ^ xb)];
                uint32_t b1 = B[n * 64 + ((lw + 4) ^ xb)];
                asm volatile(
                    "mma.sync.aligned.m16n8k16.row.col.f32.bf16.bf16.f32 "
                    "{%0,%1,%2,%3}, {%4,%5,%6,%7}, {%8,%9}, {%0,%1,%2,%3};"
                    : "+f"(d[nt][0]), "+f"(d[nt][1]), "+f"(d[nt][2]), "+f"(d[nt][3])
                    : "r"(a0), "r"(a1), "r"(a2), "r"(a3), "r"(b0), "r"(b1));
            }
        }
    }

    // epilogue: store rows + per-row sum-of-squares -> p score
    float sq0 = 0.f, sq1 = 0.f;
    int row0 = rowbase + r0, row1 = rowbase + r1;
#pragma unroll
    for (int nt = 0; nt < NTL; nt++) {
        sq0 += d[nt][0] * d[nt][0] + d[nt][1] * d[nt][1];
        sq1 += d[nt][2] * d[nt][2] + d[nt][3] * d[nt][3];
        if (row0 < NN)
            *(float2*)&g_ft[row0 * OUTC + nt * 8 + 2 * t] = make_float2(d[nt][0], d[nt][1]);
        if (row1 < NN)
            *(float2*)&g_ft[row1 * OUTC + nt * 8 + 2 * t] = make_float2(d[nt][2], d[nt][3]);
    }
    sq0 += __shfl_xor_sync(0xffffffffu, sq0, 1);
    sq0 += __shfl_xor_sync(0xffffffffu, sq0, 2);
    sq1 += __shfl_xor_sync(0xffffffffu, sq1, 1);
    sq1 += __shfl_xor_sync(0xffffffffu, sq1, 2);
    if (t == 0) {
        if (row0 < NN) {
            float nrm = fmaxf(sqrtf(sq0), 1e-8f);
            float cs  = sq0 / (nrm * nrm);
            g_p[row0] = (cs >= 0.1f) ? cs : 1e-6f;
        }
        if (row1 < NN) {
            float nrm = fmaxf(sqrtf(sq1), 1e-8f);
            float cs  = sq1 / (nrm * nrm);
            g_p[row1] = (cs >= 0.1f) ? cs : 1e-6f;
        }
    }
}

// ---------------- aggregation: one-pass warp-per-node ------------------------
// Softmax weight p[src]/S with S = sum p[src] enters linearly, so accumulate
// acc += p*ft and S += p in one pass and scale by 1/S at the end. S is
// warp-uniform (all lanes walk the same edges) -> no reduction needed.
template <int OUTC, bool LN, bool TO_X>
__global__ void __launch_bounds__(256) k_agg(const float* __restrict__ bias,
                                             const float* __restrict__ lng,
                                             const float* __restrict__ lnb,
                                             float* __restrict__ OUT) {
    constexpr int VEC = OUTC / 32;
    int warp = threadIdx.x >> 5, lane = threadIdx.x & 31;
    int node = blockIdx.x * 8 + warp;
    if (node >= NN) return;
    int b = g_rowptr[node], e = g_rowptr[node + 1];

    float S = 0.f;
    float acc[VEC];
#pragma unroll
    for (int i = 0; i < VEC; i++) acc[i] = 0.f;

#pragma unroll 8
    for (int j = b; j < e; j++) {
        int s = g_csrsrc[j];                 // uniform across warp
        float p = g_p[s];                    // broadcast load
        S += p;
        if constexpr (VEC == 4) {
            float4 f = *(const float4*)&g_ft[s * OUTC + lane * 4];
            acc[0] += p * f.x; acc[1] += p * f.y;
            acc[2] += p * f.z; acc[3] += p * f.w;
        } else {
            float2 f = *(const float2*)&g_ft[s * OUTC + lane * 2];
            acc[0] += p * f.x; acc[1] += p * f.y;
        }
    }
    float rS = (S > 0.f) ? (1.f / S) : 0.f;

    float v[VEC];
#pragma unroll
    for (int i = 0; i < VEC; i++) v[i] = acc[i] * rS + bias[lane * VEC + i];

    if constexpr (LN) {
        float s = 0.f;
#pragma unroll
        for (int i = 0; i < VEC; i++) s += v[i];
#pragma unroll
        for (int off = 16; off > 0; off >>= 1) s += __shfl_xor_sync(0xffffffffu, s, off);
        float mu = s * (1.0f / OUTC);
        float vs = 0.f;
#pragma unroll
        for (int i = 0; i < VEC; i++) { float dd = v[i] - mu; vs += dd * dd; }
#pragma unroll
        for (int off = 16; off > 0; off >>= 1) vs += __shfl_xor_sync(0xffffffffu, vs, off);
        float inv = rsqrtf(vs * (1.0f / OUTC) + 1e-5f);
        float* dstp = TO_X ? (float*)g_x : OUT;
#pragma unroll
        for (int i = 0; i < VEC; i++) {
            int c = lane * VEC + i;
            float y = (v[i] - mu) * inv * lng[c] + lnb[c];
            dstp[node * OUTC + c] = fmaxf(y, 0.f);
        }
    } else {
        float* dstp = TO_X ? (float*)g_x : OUT;
#pragma unroll
        for (int i = 0; i < VEC; i++) dstp[node * OUTC + lane * VEC + i] = v[i];
    }
}

// ---------------- launch -----------------------------------------------------
extern "C" void kernel_launch(void* const* d_in, const int* in_sizes, int n_in,
                              void* d_out, int out_size) {
    const float* feat = (const float*)d_in[0];
    const int*   src  = (const int*)d_in[1];
    const int*   dst  = (const int*)d_in[2];
    const float* W0   = (const float*)d_in[3];
    const float* b0   = (const float*)d_in[4];
    const float* W1   = (const float*)d_in[5];
    const float* b1   = (const float*)d_in[6];
    const float* W2   = (const float*)d_in[7];
    const float* b2   = (const float*)d_in[8];
    const float* ln1g = (const float*)d_in[9];
    const float* ln1b = (const float*)d_in[10];
    const float* ln2g = (const float*)d_in[11];
    const float* ln2b = (const float*)d_in[12];
    float* out = (float*)d_out;

    const int GE4 = (NE / 4 + 255) / 256;   // 782
    const int GA  = (NN + 7) / 8;           // 6250
    const int S128 = (16384 + 2 * 128 * 64) * 4;   // 128KB
    const int S64  = (16384 + 2 * 64 * 64) * 4;    // 96KB

    cudaFuncSetAttribute(k_hgemm<128, false, 0>,
                         cudaFuncAttributeMaxDynamicSharedMemorySize, S128);
    cudaFuncSetAttribute(k_hgemm<128, true, 1>,
                         cudaFuncAttributeMaxDynamicSharedMemorySize, S128);
    cudaFuncSetAttribute(k_hgemm<64, true, 2>,
                         cudaFuncAttributeMaxDynamicSharedMemorySize, S64);

    // fused W prep + count, then scan + scatter (deterministic every call)
    k_wprep_count<<<160 + GE4, 256>>>(W0, W1, W2, dst);
    k_scan<<<1, 1024>>>();
    k_scatter<<<GE4, 256>>>(src, dst);

    // layer 1: feat -> g_x  (conv + LN + ReLU)
    k_hgemm<128, false, 0><<<NTILES, 256, S128>>>(feat);
    k_agg<128, true, true><<<GA, 256>>>(b0, ln1g, ln1b, nullptr);

    // layer 2: g_x -> g_x
    k_hgemm<128, true, 1><<<NTILES, 256, S128>>>(nullptr);
    k_agg<128, true, true><<<GA, 256>>>(b1, ln2g, ln2b, nullptr);

    // layer 3: g_x -> d_out (no LN/ReLU)
    k_hgemm<64, true, 2><<<NTILES, 256, S64>>>(nullptr);
    k_agg<64, false, false><<<GA, 256>>>(b2, nullptr, nullptr, out);
}

// round 17
// speedup vs baseline: 1.2727x; 1.0509x over previous
#include <cuda_runtime.h>
#include <cuda_bf16.h>
#include <cstdint>

#define NN 50000
#define NE 800000
#define NTILES 391        // tiles of 128 rows

// ---------------- scratch (device globals: no allocations allowed) ----------
__device__ __align__(16) float g_ft[NN * 128];   // per-layer GEMM output
__device__ __align__(16) float g_x[NN * 128];    // layer activations
__device__ float g_p[NN];                        // exp(attention logit) = clamped cos
__device__ int g_rowptr[NN + 1];
__device__ int g_cnt[NN];                        // zero at load; re-zeroed by k_scan
__device__ int g_cursor[NN];
__device__ int g_csrsrc[NE];
// W images: bf16 hi/lo, transposed [n][k], XOR-swizzled word layout
__device__ __align__(16) unsigned short g_whi[3][16384];
__device__ __align__(16) unsigned short g_wlo[3][16384];

#define CVT_BF16X2(res, even, odd) asm("cvt.rn.satfinite.bf16x2.f32 %0, %1, %2;" \
    : "=r"(res) : "f"(odd), "f"(even))
#define CP_A16(dst, src) asm volatile("cp.async.cg.shared.global [%0], [%1], 16;" \
    :: "r"(dst), "l"(src))
#define CP_COMMIT() asm volatile("cp.async.commit_group;")
#define CP_WAIT0()  asm volatile("cp.async.wait_group 0;")

__device__ __forceinline__ uint32_t smem_u32(const void* p) {
    uint32_t a;
    asm("{ .reg .u64 t; cvta.to.shared.u64 t, %1; cvt.u32.u64 %0, t; }" : "=r"(a) : "l"(p));
    return a;
}

// ---------------- fused W prep + degree count --------------------------------
// blocks [0,160): split fp32 W -> bf16 hi/lo swizzled images
// blocks [160,160+782): count edge degrees, 4 edges/thread (ILP)
__global__ void k_wprep_count(const float* __restrict__ W0,
                              const float* __restrict__ W1,
                              const float* __restrict__ W2,
                              const int* __restrict__ dst) {
    if (blockIdx.x < 160) {
        int idx = blockIdx.x * 256 + threadIdx.x;
        if (idx >= 16384 * 2 + 8192) return;
        int layer, e, outc;
        const float* W;
        if (idx < 16384)      { layer = 0; e = idx;         outc = 128; W = W0; }
        else if (idx < 32768) { layer = 1; e = idx - 16384; outc = 128; W = W1; }
        else                  { layer = 2; e = idx - 32768; outc = 64;  W = W2; }
        int k = e & 127, n = e >> 7;
        float w = W[k * outc + n];
        __nv_bfloat16 h = __float2bfloat16(w);
        float fh = __bfloat162float(h);
        __nv_bfloat16 l = __float2bfloat16(w - fh);
        int word = n * 64 + (((k >> 1) & 63) ^ ((n & 7) << 2) ^ ((n >> 3) & 3));
        ((unsigned short*)g_whi[layer])[word * 2 + (k & 1)] = __bfloat16_as_ushort(h);
        ((unsigned short*)g_wlo[layer])[word * 2 + (k & 1)] = __bfloat16_as_ushort(l);
    } else {
        int e4 = (blockIdx.x - 160) * 256 + threadIdx.x;
        if (e4 < NE / 4) {
            int4 d = ((const int4*)dst)[e4];
            atomicAdd(&g_cnt[d.x], 1);
            atomicAdd(&g_cnt[d.y], 1);
            atomicAdd(&g_cnt[d.z], 1);
            atomicAdd(&g_cnt[d.w], 1);
        }
    }
}

// single-block scan, shfl-based, 4 elems/thread; re-zeros g_cnt after reading
__global__ void __launch_bounds__(1024) k_scan() {
    __shared__ int wsum[32];
    __shared__ int s_carry, s_tot;
    int tid = threadIdx.x, lane = tid & 31, warp = tid >> 5;
    if (tid == 0) s_carry = 0;
    __syncthreads();
    for (int base = 0; base < NN; base += 4096) {
        int i0 = base + tid * 4;
        int v[4];
#pragma unroll
        for (int j = 0; j < 4; j++) {
            int i = i0 + j;
            v[j] = (i < NN) ? g_cnt[i] : 0;
            if (i < NN) g_cnt[i] = 0;   // restore invariant for next call
        }
        int t = v[0] + v[1] + v[2] + v[3];
        int inc = t;
#pragma unroll
        for (int off = 1; off < 32; off <<= 1) {
            int n = __shfl_up_sync(0xffffffffu, inc, off);
            if (lane >= off) inc += n;
        }
        if (lane == 31) wsum[warp] = inc;
        __syncthreads();
        if (warp == 0) {
            int w = wsum[lane];
            int wi = w;
#pragma unroll
            for (int off = 1; off < 32; off <<= 1) {
                int n = __shfl_up_sync(0xffffffffu, wi, off);
                if (lane >= off) wi += n;
            }
            if (lane == 31) s_tot = wi;
            wsum[lane] = wi - w;
        }
        __syncthreads();
        int run = s_carry + wsum[warp] + (inc - t);
#pragma unroll
        for (int j = 0; j < 4; j++) {
            int i = i0 + j;
            if (i < NN) { g_rowptr[i] = run; g_cursor[i] = run; }
            run += v[j];
        }
        __syncthreads();
        if (tid == 0) s_carry += s_tot;
        __syncthreads();
    }
    if (tid == 0) g_rowptr[NN] = s_carry;
}

__global__ void k_scatter(const int* __restrict__ src, const int* __restrict__ dst) {
    int e4 = blockIdx.x * blockDim.x + threadIdx.x;
    if (e4 < NE / 4) {
        int4 d = ((const int4*)dst)[e4];
        int4 s = ((const int4*)src)[e4];
        int p0 = atomicAdd(&g_cursor[d.x], 1);
        int p1 = atomicAdd(&g_cursor[d.y], 1);
        int p2 = atomicAdd(&g_cursor[d.z], 1);
        int p3 = atomicAdd(&g_cursor[d.w], 1);
        g_csrsrc[p0] = s.x;
        g_csrsrc[p1] = s.y;
        g_csrsrc[p2] = s.z;
        g_csrsrc[p3] = s.w;
    }
}

// ---------------- HMMA GEMM: ft = X @ W (bf16 hi/lo split, 3 passes) --------
// Block = 256 thr / 8 warps, 128-row tile; K processed in 2 chunks of 64 so
// resident smem is 64KB (48KB for OUTC=64) -> 3-4 CTAs/SM, single wave.
// mma.sync.m16n8k16.row.col f32.bf16.bf16 (sm_80 ISA).
template <int OUTC, bool FROM_X, int LIDX>
__global__ void __launch_bounds__(256, 3) k_hgemm(const float* __restrict__ Xin) {
    constexpr int NTL = OUTC / 8;            // n-tiles per warp (16 or 8)
    constexpr int CW  = OUTC * 32;           // W chunk words per image
    extern __shared__ __align__(16) uint32_t sm[];
    uint32_t* sXH = sm;                      // 4096 words (16KB)
    uint32_t* sXL = sm + 4096;               // 4096 words
    uint32_t* sWH = sm + 8192;               // CW words
    uint32_t* sWL = sm + 8192 + CW;          // CW words

    const float* X = FROM_X ? (const float*)g_x : Xin;
    int tid = threadIdx.x, wid = tid >> 5, lane = tid & 31;
    int rowbase = blockIdx.x * 128;

    int g = lane >> 2, t = lane & 3;
    int r0 = wid * 16 + g;                   // rows r0 (c0,c1) and r0+8 (c2,c3)
    int r1 = r0 + 8;
    int xm0 = ((r0 & 7) << 2) ^ ((r0 >> 3) & 3);
    int xm1 = ((r1 & 7) << 2) ^ ((r1 >> 3) & 3);
    int base0 = r0 * 32, base1 = r1 * 32;

    // accumulators: warp tile 16 x OUTC (persist across K chunks)
    float d[NTL][4];
#pragma unroll
    for (int nt = 0; nt < NTL; nt++)
#pragma unroll
        for (int j = 0; j < 4; j++) d[nt][j] = 0.f;

    uint32_t hdst = smem_u32(sWH);
    uint32_t ldst = smem_u32(sWL);
    const uint32_t* hsrc = (const uint32_t*)g_whi[LIDX];
    const uint32_t* lsrc = (const uint32_t*)g_wlo[LIDX];

#pragma unroll 1
    for (int c = 0; c < 2; c++) {
        // W chunk via cp.async: image words n*64 + c*32 + [0,32) -> smem n*32+
        for (int i = tid; i < CW / 4; i += 256) {
            int idx = i * 4;
            int n = idx >> 5, off = idx & 31;
            int gw = n * 64 + c * 32 + off;
            CP_A16(hdst + i * 16, hsrc + gw);
            CP_A16(ldst + i * 16, lsrc + gw);
        }
        CP_COMMIT();

        // X chunk: fp32 -> bf16 hi/lo, swizzled store (warp per row: no conflicts)
#pragma unroll 4
        for (int it = 0; it < 16; it++) {
            int wl = tid + 256 * it;         // 0..4095 over 128 rows x 32 words
            int r = wl >> 5, w = wl & 31;
            int gr = rowbase + r;
            float2 x = (gr < NN) ? *(const float2*)&X[gr * 128 + c * 64 + 2 * w]
                                 : make_float2(0.f, 0.f);
            uint32_t h, l;
            CVT_BF16X2(h, x.x, x.y);
            float hx = __uint_as_float(h << 16);
            float hy = __uint_as_float(h & 0xFFFF0000u);
            CVT_BF16X2(l, x.x - hx, x.y - hy);
            int phys = r * 32 + (w ^ ((r & 7) << 2) ^ ((r >> 3) & 3));
            sXH[phys] = h;
            sXL[phys] = l;
        }
        CP_WAIT0();
        __syncthreads();

#pragma unroll 1
        for (int pass = 0; pass < 3; pass++) {   // hi*hi, hi*lo, lo*hi
            const uint32_t* A = (pass == 2) ? sXL : sXH;
            const uint32_t* B = (pass == 1) ? sWL : sWH;
#pragma unroll 1
            for (int ks = 0; ks < 4; ks++) {
                int lw = ks * 8 + t;
                uint32_t a0 = A[base0 + (lw ^ xm0)];
                uint32_t a1 = A[base1 + (lw ^ xm1)];
                uint32_t a2 = A[base0 + ((lw + 4) ^ xm0)];
                uint32_t a3 = A[base1 + ((lw + 4) ^ xm1)];
#pragma unroll
                for (int nt = 0; nt < NTL; nt++) {
                    int n = nt * 8 + g;
                    int xb = ((n & 7) << 2) ^ (nt & 3);
                    uint32_t b0 = B[n * 32 + (lw ^ xb)];
                    uint32_t b1 = B[n * 32 + ((lw + 4) ^ xb)];
                    asm volatile(
                        "mma.sync.aligned.m16n8k16.row.col.f32.bf16.bf16.f32 "
                        "{%0,%1,%2,%3}, {%4,%5,%6,%7}, {%8,%9}, {%0,%1,%2,%3};"
                        : "+f"(d[nt][0]), "+f"(d[nt][1]), "+f"(d[nt][2]), "+f"(d[nt][3])
                        : "r"(a0), "r"(a1), "r"(a2), "r"(a3), "r"(b0), "r"(b1));
                }
            }
        }
        __syncthreads();   // before next chunk overwrites smem
    }

    // epilogue: store rows + per-row sum-of-squares -> p score
    float sq0 = 0.f, sq1 = 0.f;
    int row0 = rowbase + r0, row1 = rowbase + r1;
#pragma unroll
    for (int nt = 0; nt < NTL; nt++) {
        sq0 += d[nt][0] * d[nt][0] + d[nt][1] * d[nt][1];
        sq1 += d[nt][2] * d[nt][2] + d[nt][3] * d[nt][3];
        if (row0 < NN)
            *(float2*)&g_ft[row0 * OUTC + nt * 8 + 2 * t] = make_float2(d[nt][0], d[nt][1]);
        if (row1 < NN)
            *(float2*)&g_ft[row1 * OUTC + nt * 8 + 2 * t] = make_float2(d[nt][2], d[nt][3]);
    }
    sq0 += __shfl_xor_sync(0xffffffffu, sq0, 1);
    sq0 += __shfl_xor_sync(0xffffffffu, sq0, 2);
    sq1 += __shfl_xor_sync(0xffffffffu, sq1, 1);
    sq1 += __shfl_xor_sync(0xffffffffu, sq1, 2);
    if (t == 0) {
        if (row0 < NN) {
            float nrm = fmaxf(sqrtf(sq0), 1e-8f);
            float cs  = sq0 / (nrm * nrm);
            g_p[row0] = (cs >= 0.1f) ? cs : 1e-6f;
        }
        if (row1 < NN) {
            float nrm = fmaxf(sqrtf(sq1), 1e-8f);
            float cs  = sq1 / (nrm * nrm);
            g_p[row1] = (cs >= 0.1f) ? cs : 1e-6f;
        }
    }
}

// ---------------- aggregation: one-pass warp-per-node ------------------------
// Softmax weight p[src]/S enters linearly: accumulate acc += p*ft and S += p
// in one pass, scale by 1/S at the end. S is warp-uniform (no reduction).
template <int OUTC, bool LN, bool TO_X>
__global__ void __launch_bounds__(256) k_agg(const float* __restrict__ bias,
                                             const float* __restrict__ lng,
                                             const float* __restrict__ lnb,
                                             float* __restrict__ OUT) {
    constexpr int VEC = OUTC / 32;
    int warp = threadIdx.x >> 5, lane = threadIdx.x & 31;
    int node = blockIdx.x * 8 + warp;
    if (node >= NN) return;
    int b = g_rowptr[node], e = g_rowptr[node + 1];

    float S = 0.f;
    float acc[VEC];
#pragma unroll
    for (int i = 0; i < VEC; i++) acc[i] = 0.f;

#pragma unroll 8
    for (int j = b; j < e; j++) {
        int s = g_csrsrc[j];                 // uniform across warp
        float p = g_p[s];                    // broadcast load
        S += p;
        if constexpr (VEC == 4) {
            float4 f = *(const float4*)&g_ft[s * OUTC + lane * 4];
            acc[0] += p * f.x; acc[1] += p * f.y;
            acc[2] += p * f.z; acc[3] += p * f.w;
        } else {
            float2 f = *(const float2*)&g_ft[s * OUTC + lane * 2];
            acc[0] += p * f.x; acc[1] += p * f.y;
        }
    }
    float rS = (S > 0.f) ? (1.f / S) : 0.f;

    float v[VEC];
#pragma unroll
    for (int i = 0; i < VEC; i++) v[i] = acc[i] * rS + bias[lane * VEC + i];

    if constexpr (LN) {
        float s = 0.f;
#pragma unroll
        for (int i = 0; i < VEC; i++) s += v[i];
#pragma unroll
        for (int off = 16; off > 0; off >>= 1) s += __shfl_xor_sync(0xffffffffu, s, off);
        float mu = s * (1.0f / OUTC);
        float vs = 0.f;
#pragma unroll
        for (int i = 0; i < VEC; i++) { float dd = v[i] - mu; vs += dd * dd; }
#pragma unroll
        for (int off = 16; off > 0; off >>= 1) vs += __shfl_xor_sync(0xffffffffu, vs, off);
        float inv = rsqrtf(vs * (1.0f / OUTC) + 1e-5f);
        float* dstp = TO_X ? (float*)g_x : OUT;
#pragma unroll
        for (int i = 0; i < VEC; i++) {
            int c = lane * VEC + i;
            float y = (v[i] - mu) * inv * lng[c] + lnb[c];
            dstp[node * OUTC + c] = fmaxf(y, 0.f);
        }
    } else {
        float* dstp = TO_X ? (float*)g_x : OUT;
#pragma unroll
        for (int i = 0; i < VEC; i++) dstp[node * OUTC + lane * VEC + i] = v[i];
    }
}

// ---------------- launch -----------------------------------------------------
extern "C" void kernel_launch(void* const* d_in, const int* in_sizes, int n_in,
                              void* d_out, int out_size) {
    const float* feat = (const float*)d_in[0];
    const int*   src  = (const int*)d_in[1];
    const int*   dst  = (const int*)d_in[2];
    const float* W0   = (const float*)d_in[3];
    const float* b0   = (const float*)d_in[4];
    const float* W1   = (const float*)d_in[5];
    const float* b1   = (const float*)d_in[6];
    const float* W2   = (const float*)d_in[7];
    const float* b2   = (const float*)d_in[8];
    const float* ln1g = (const float*)d_in[9];
    const float* ln1b = (const float*)d_in[10];
    const float* ln2g = (const float*)d_in[11];
    const float* ln2b = (const float*)d_in[12];
    float* out = (float*)d_out;

    const int GE4 = (NE / 4 + 255) / 256;   // 782
    const int GA  = (NN + 7) / 8;           // 6250
    const int S128 = (8192 + 2 * 128 * 32) * 4;   // 64KB
    const int S64  = (8192 + 2 * 64 * 32) * 4;    // 48KB

    cudaFuncSetAttribute(k_hgemm<128, false, 0>,
                         cudaFuncAttributeMaxDynamicSharedMemorySize, S128);
    cudaFuncSetAttribute(k_hgemm<128, true, 1>,
                         cudaFuncAttributeMaxDynamicSharedMemorySize, S128);
    cudaFuncSetAttribute(k_hgemm<64, true, 2>,
                         cudaFuncAttributeMaxDynamicSharedMemorySize, S64);

    // fused W prep + count, then scan + scatter (deterministic every call)
    k_wprep_count<<<160 + GE4, 256>>>(W0, W1, W2, dst);
    k_scan<<<1, 1024>>>();
    k_scatter<<<GE4, 256>>>(src, dst);

    // layer 1: feat -> g_x  (conv + LN + ReLU)
    k_hgemm<128, false, 0><<<NTILES, 256, S128>>>(feat);
    k_agg<128, true, true><<<GA, 256>>>(b0, ln1g, ln1b, nullptr);

    // layer 2: g_x -> g_x
    k_hgemm<128, true, 1><<<NTILES, 256, S128>>>(nullptr);
    k_agg<128, true, true><<<GA, 256>>>(b1, ln2g, ln2b, nullptr);

    // layer 3: g_x -> d_out (no LN/ReLU)
    k_hgemm<64, true, 2><<<NTILES, 256, S64>>>(nullptr);
    k_agg<64, false, false><<<GA, 256>>>(b2, nullptr, nullptr, out);
}